// round 15
// baseline (speedup 1.0000x reference)
#include <cuda_runtime.h>
#include <cuda_fp8.h>
#include <cstdint>
#include <math.h>

#define Nn 8192
#define NJOBS 1056                     // (bi,BJ): 64 x 32, BJ >= bi>>1
#define NCTA 148                       // one wave, co-resident
#define TSA 16384                      // A tile: 128 rows x 128B
#define TSB 32768                      // B tile: 256 cols x 128B
#define NEG_C 2.3195228352514835e-16f  /* exp(-36) */

// SMEM map (dynamic): A double [0,32K) | B double [32K,96K) | tgtA x2 | tgtB x2
#define SM_B    32768
#define SM_TGA  98304
#define SM_TGB  99328
#define SM_TOT  101376

__device__ unsigned char g_xq[Nn * 128]; // normalized e4m3 rows (128B/row)
__device__ int   g_tgt[Nn];
__device__ float g_acc[3 * Nn];          // sp(excl diag) | sn | cn
__device__ float g_part[32];
__device__ int   g_b1, g_b2, g_b3;       // spin barriers (reset at kernel end)

// ---------------- helpers ----------------
__device__ __forceinline__ uint32_t s2u(const void* p) {
    uint32_t a;
    asm("{ .reg .u64 t; cvta.to.shared.u64 t, %1; cvt.u32.u64 %0, t; }" : "=r"(a) : "l"(p));
    return a;
}
__device__ __forceinline__ void cp16(uint32_t s, const void* g) {
    asm volatile("cp.async.cg.shared.global [%0], [%1], 16;"
                 :: "r"(s), "l"(__cvta_generic_to_global(g)) : "memory");
}
__device__ __forceinline__ void cp_commit() {
    asm volatile("cp.async.commit_group;" ::: "memory");
}
__device__ __forceinline__ void cp_wait0() {
    asm volatile("cp.async.wait_group 0;" ::: "memory");
}
__device__ __forceinline__ void cp_wait1() {
    asm volatile("cp.async.wait_group 1;" ::: "memory");
}
__device__ __forceinline__ void ldsm4(uint32_t (&r)[4], uint32_t addr) {
    asm volatile("ldmatrix.sync.aligned.m8n8.x4.shared.b16 {%0,%1,%2,%3}, [%4];"
                 : "=r"(r[0]), "=r"(r[1]), "=r"(r[2]), "=r"(r[3]) : "r"(addr));
}
__device__ __forceinline__ void mma_fp8(float (&c)[4], const uint32_t* a,
                                        uint32_t b0, uint32_t b1) {
    asm volatile(
        "mma.sync.aligned.m16n8k32.row.col.f32.e4m3.e4m3.f32 "
        "{%0,%1,%2,%3}, {%4,%5,%6,%7}, {%8,%9}, {%0,%1,%2,%3};"
        : "+f"(c[0]), "+f"(c[1]), "+f"(c[2]), "+f"(c[3])
        : "r"(a[0]), "r"(a[1]), "r"(a[2]), "r"(a[3]), "r"(b0), "r"(b1));
}
__device__ __forceinline__ uint32_t soff8(int row, int ch) {
    return (uint32_t)((row << 7) + ((ch ^ (row & 7)) << 4));
}
// job offset: first flat index of row bi;  jobs in row bi: 32 - (bi>>1)
__device__ __forceinline__ int joff(int b) {
    return b == 0 ? 0 : 32 * b - ((b - 1) * (b - 1)) / 4;
}
__device__ __forceinline__ void decode(int J, int& bi, int& BJ) {
    int b = 64 - (int)(2.0f * sqrtf(fmaxf(1024.0f - (float)J, 0.0f)));
    if (b > 63) b = 63;
    if (b < 0) b = 0;
    while (b < 63 && joff(b + 1) <= J) b++;
    while (b > 0 && joff(b) > J) b--;
    bi = b;
    BJ = (b >> 1) + (J - joff(b));
}
__device__ __forceinline__ void gbar(int* ctr, int tid) {
    __threadfence();
    __syncthreads();
    if (tid == 0) {
        atomicAdd(ctr, 1);
        long long n = 0;
        while (*(volatile int*)ctr < NCTA && n < (1LL << 26)) { __nanosleep(40); n++; }
    }
    __syncthreads();
    __threadfence();
}

// ---------------- fused: prep + triangle fp8 GEMM (128x256 jobs) + reduction ----------
extern __shared__ char smem[];

__global__ void __launch_bounds__(512) k_all(const float* __restrict__ x,
                                             const int* __restrict__ t,
                                             float* __restrict__ out) {
    int tid = threadIdx.x, wid = tid >> 5, lane = tid & 31;
    int bid = blockIdx.x;
    uint32_t sb = s2u(smem);

    // ===== phase 1: zero acc, copy targets, normalize + e4m3 =====
    for (int idx = bid * 512 + tid; idx < 3 * Nn; idx += NCTA * 512) g_acc[idx] = 0.f;
    for (int idx = bid * 512 + tid; idx < Nn; idx += NCTA * 512) g_tgt[idx] = t[idx];
    for (int row = bid * 16 + wid; row < Nn; row += NCTA * 16) {
        float4 v = reinterpret_cast<const float4*>(x + (size_t)row * 128)[lane];
        float s = v.x * v.x + v.y * v.y + v.z * v.z + v.w * v.w;
#pragma unroll
        for (int o = 16; o; o >>= 1) s += __shfl_xor_sync(0xffffffffu, s, o);
        float inv = rsqrtf(s);
        __nv_fp8x2_storage_t lo = __nv_cvt_float2_to_fp8x2(
            make_float2(v.x * inv, v.y * inv), __NV_SATFINITE, __NV_E4M3);
        __nv_fp8x2_storage_t hi = __nv_cvt_float2_to_fp8x2(
            make_float2(v.z * inv, v.w * inv), __NV_SATFINITE, __NV_E4M3);
        reinterpret_cast<uint32_t*>(g_xq)[row * 32 + lane] =
            (uint32_t)lo | ((uint32_t)hi << 16);
    }
    gbar(&g_b1, tid);

    // ===== phase 2: triangle GEMM, 128x256 jobs =====
    const char* gX = (const char*)g_xq;
    int m0 = (wid & 3) * 32, n0 = (wid >> 2) * 64;

    int nstart = (int)(((long long)bid * NJOBS) / NCTA);
    int nend   = (int)(((long long)(bid + 1) * NJOBS) / NCTA);

    int bi, BJ;
    decode(nstart, bi, BJ);

    // prologue: A(bi), tgtA -> parity 0; B(BJ), tgtB -> parity 0
#pragma unroll
    for (int q = 0; q < 2; q++) {
        int g = tid + 512 * q, row = g >> 3, ch = g & 7;
        cp16(sb + soff8(row, ch), gX + (size_t)(bi * 128 + row) * 128 + ch * 16);
    }
#pragma unroll
    for (int q = 0; q < 4; q++) {
        int g = tid + 512 * q, row = g >> 3, ch = g & 7;
        cp16(sb + SM_B + soff8(row, ch), gX + (size_t)(BJ * 256 + row) * 128 + ch * 16);
    }
    if (tid < 32)       cp16(sb + SM_TGA + tid * 16, (const char*)(g_tgt + bi * 128) + tid * 16);
    else if (tid < 96)  cp16(sb + SM_TGB + (tid - 32) * 16,
                             (const char*)(g_tgt + BJ * 256) + (tid - 32) * 16);
    cp_commit();

    int pa = 0, pb = 0;
    for (int L = nstart; L < nend; L++) {
        bool hn = (L + 1 < nend);
        bool aswap = false;
        if (hn) {
            int bin = bi, BJn = BJ + 1;
            if (BJn == 32) { bin = bi + 1; BJn = bin >> 1; }
            if (bin != bi) {
                aswap = true;
#pragma unroll
                for (int q = 0; q < 2; q++) {
                    int g = tid + 512 * q, row = g >> 3, ch = g & 7;
                    cp16(sb + (pa ^ 1) * TSA + soff8(row, ch),
                         gX + (size_t)(bin * 128 + row) * 128 + ch * 16);
                }
                if (tid < 32)
                    cp16(sb + SM_TGA + (pa ^ 1) * 512 + tid * 16,
                         (const char*)(g_tgt + bin * 128) + tid * 16);
            }
#pragma unroll
            for (int q = 0; q < 4; q++) {
                int g = tid + 512 * q, row = g >> 3, ch = g & 7;
                cp16(sb + SM_B + (pb ^ 1) * TSB + soff8(row, ch),
                     gX + (size_t)(BJn * 256 + row) * 128 + ch * 16);
            }
            if (tid >= 32 && tid < 96)
                cp16(sb + SM_TGB + (pb ^ 1) * 1024 + (tid - 32) * 16,
                     (const char*)(g_tgt + BJn * 256) + (tid - 32) * 16);
            cp_commit();
        }

        if (hn) cp_wait1(); else cp_wait0();
        __syncthreads();

        int i0 = bi * 128, j0 = BJ * 256;

        // ---- GEMM: warp slice 32x64 of the 128x256 job ----
        float acc[2][8][4];
#pragma unroll
        for (int mf = 0; mf < 2; mf++)
#pragma unroll
            for (int nf = 0; nf < 8; nf++)
#pragma unroll
                for (int e2 = 0; e2 < 4; e2++) acc[mf][nf][e2] = 0.f;

        uint32_t Ab = sb + pa * TSA, Bb = sb + SM_B + pb * TSB;
        {
            int arow = m0 + ((lane >> 3) & 1) * 8 + (lane & 7);
            int ach  = (lane >> 4);
            int brow = n0 + (lane >> 4) * 8 + (lane & 7);
            int bch  = ((lane >> 3) & 1);
#pragma unroll
            for (int ks = 0; ks < 4; ks++) {
                uint32_t aF[2][4], bF[4][4];
                ldsm4(aF[0], Ab + soff8(arow,      ks * 2 + ach));
                ldsm4(aF[1], Ab + soff8(arow + 16, ks * 2 + ach));
#pragma unroll
                for (int nf2 = 0; nf2 < 4; nf2++)
                    ldsm4(bF[nf2], Bb + soff8(brow + nf2 * 16, ks * 2 + bch));
#pragma unroll
                for (int mf = 0; mf < 2; mf++)
#pragma unroll
                    for (int nf2 = 0; nf2 < 4; nf2++) {
                        mma_fp8(acc[mf][nf2 * 2 + 0], aF[mf], bF[nf2][0], bF[nf2][1]);
                        mma_fp8(acc[mf][nf2 * 2 + 1], aF[mf], bF[nf2][2], bF[nf2][3]);
                    }
            }
        }

        __syncthreads();  // ldsm reads done -> next prefetch may overwrite

        // ---- epilogue: frag early-out, smem targets, uniform gj>gi rule ----
        const int* tgA = reinterpret_cast<const int*>(smem + SM_TGA + pa * 512);
        const int* tgB = reinterpret_cast<const int*>(smem + SM_TGB + pb * 1024);
#pragma unroll
        for (int nf2 = 0; nf2 < 4; nf2++)
#pragma unroll
            for (int par = 0; par < 2; par++) {
                int colb = n0 + nf2 * 16 + par * 8 + (lane & 3) * 2;
                int nf = nf2 * 2 + par;
#pragma unroll
                for (int mf = 0; mf < 2; mf++) {
                    const float* a4 = acc[mf][nf];
                    float m4 = fmaxf(fmaxf(a4[0], a4[1]), fmaxf(a4[2], a4[3]));
                    if (m4 > 0.25f) {              // rare (~1% of frags)
#pragma unroll
                        for (int h = 0; h < 2; h++) {
                            int rl = m0 + mf * 16 + h * 8 + (lane >> 2);
#pragma unroll
                            for (int e2 = 0; e2 < 2; e2++) {
                                float s = a4[h * 2 + e2];
                                if (s > 0.25f) {
                                    int gi = i0 + rl, gj = j0 + colb + e2;
                                    if (gj > gi) {  // strict upper triangle, once per pair
                                        if (tgA[rl] == tgB[colb + e2]) {
                                            float ev = __expf(fmaf(64.f * (1.25f - s),
                                                                   s - 0.75f, -4.f));
                                            atomicAdd(&g_acc[gi], ev);
                                            atomicAdd(&g_acc[gj], ev);
                                        } else {
                                            float tt = s - 0.25f;
                                            float ev = __expf(fmaf(64.f * tt, tt, -36.f));
                                            atomicAdd(&g_acc[Nn + gi], ev);
                                            atomicAdd(&g_acc[2 * Nn + gi], 1.f);
                                            atomicAdd(&g_acc[Nn + gj], ev);
                                            atomicAdd(&g_acc[2 * Nn + gj], 1.f);
                                        }
                                    }
                                }
                            }
                        }
                    }
                }
            }

        pb ^= 1;
        if (aswap) pa ^= 1;
        BJ++;
        if (BJ == 32) { bi++; BJ = bi >> 1; }
    }
    gbar(&g_b2, tid);

    // ===== phase 3: reduction on CTAs 0..31 =====
    if (bid < 32) {
        int*   hist = reinterpret_cast<int*>(smem);
        float* red  = reinterpret_cast<float*>(smem + 2048);
        hist[tid] = 0;
        __syncthreads();
        for (int i = tid; i < Nn; i += 512) atomicAdd(&hist[g_tgt[i]], 1);
        __syncthreads();

        float acc = 0.f;
        if (tid < 256) {
            int i = bid * 256 + tid;
            float spv = g_acc[i] + 1.0f;                          // exact diagonal term
            float below = (float)(Nn - hist[g_tgt[i]]) - g_acc[2 * Nn + i];
            float snv = g_acc[Nn + i] + below * NEG_C;
            float z = 40.f + logf(spv) + logf(snv);               // > 13
            acc = z + log1pf(__expf(-z));                         // softplus
        }
#pragma unroll
        for (int o = 16; o; o >>= 1) acc += __shfl_xor_sync(0xffffffffu, acc, o);
        if ((tid & 31) == 0) red[tid >> 5] = acc;
        __syncthreads();
        if (tid == 0) {
            float s = 0.f;
#pragma unroll
            for (int w = 0; w < 16; w++) s += red[w];
            g_part[bid] = s;
        }
    }
    __threadfence();
    __syncthreads();
    if (tid == 0) {
        atomicAdd(&g_b3, 1);
        if (bid == 0) {
            long long n = 0;
            while (*(volatile int*)&g_b3 < NCTA && n < (1LL << 26)) { __nanosleep(40); n++; }
            __threadfence();
            float s = 0.f;
#pragma unroll
            for (int w = 0; w < 32; w++) s += g_part[w];
            out[0] = s / (float)Nn;
            g_b1 = 0; g_b2 = 0; g_b3 = 0;   // clean state for next graph replay
            __threadfence();
        }
    }
}

extern "C" void kernel_launch(void* const* d_in, const int* in_sizes, int n_in,
                              void* d_out, int out_size) {
    const float* x  = (const float*)d_in[0];
    const int*   tg = (const int*)d_in[1];
    float* out = (float*)d_out;

    cudaFuncSetAttribute(k_all, cudaFuncAttributeMaxDynamicSharedMemorySize, SM_TOT);
    k_all<<<NCTA, 512, SM_TOT>>>(x, tg, out);
}

// round 17
// speedup vs baseline: 1.2196x; 1.2196x over previous
#include <cuda_runtime.h>
#include <cuda_fp8.h>
#include <cstdint>
#include <math.h>

#define Nn 8192
#define NJOBS 2080                     // 64*65/2 upper-triangle 128x128 tile pairs
#define NCTA 148                       // one wave, guaranteed co-resident
#define TS 16384                       // fp8 tile bytes: 128 rows x 128B
#define NEG_C 2.3195228352514835e-16f  /* exp(-36) */

// SMEM: A double [0,32K) | B double [32K,64K) | tgtA x2 [64K,+1K) | tgtB x2 [+1K,+2K)
#define SM_TGA  65536
#define SM_TGB  66560
#define SM_TOT  67584

__device__ unsigned char g_xq[Nn * 128]; // normalized e4m3 rows (128B/row)
__device__ int   g_tgt[Nn];
__device__ float g_acc[3 * Nn];          // sp(excl diag) | sn | cn
__device__ float g_part[32];
__device__ int   g_b1, g_b2, g_b3;       // spin barriers (reset at kernel end)

// ---------------- helpers ----------------
__device__ __forceinline__ uint32_t s2u(const void* p) {
    uint32_t a;
    asm("{ .reg .u64 t; cvta.to.shared.u64 t, %1; cvt.u32.u64 %0, t; }" : "=r"(a) : "l"(p));
    return a;
}
__device__ __forceinline__ void cp16(uint32_t s, const void* g) {
    asm volatile("cp.async.cg.shared.global [%0], [%1], 16;"
                 :: "r"(s), "l"(__cvta_generic_to_global(g)) : "memory");
}
__device__ __forceinline__ void cp_commit() {
    asm volatile("cp.async.commit_group;" ::: "memory");
}
__device__ __forceinline__ void cp_wait0() {
    asm volatile("cp.async.wait_group 0;" ::: "memory");
}
__device__ __forceinline__ void cp_wait1() {
    asm volatile("cp.async.wait_group 1;" ::: "memory");
}
__device__ __forceinline__ void ldsm4(uint32_t (&r)[4], uint32_t addr) {
    asm volatile("ldmatrix.sync.aligned.m8n8.x4.shared.b16 {%0,%1,%2,%3}, [%4];"
                 : "=r"(r[0]), "=r"(r[1]), "=r"(r[2]), "=r"(r[3]) : "r"(addr));
}
__device__ __forceinline__ void mma_fp8(float (&c)[4], const uint32_t* a,
                                        uint32_t b0, uint32_t b1) {
    asm volatile(
        "mma.sync.aligned.m16n8k32.row.col.f32.e4m3.e4m3.f32 "
        "{%0,%1,%2,%3}, {%4,%5,%6,%7}, {%8,%9}, {%0,%1,%2,%3};"
        : "+f"(c[0]), "+f"(c[1]), "+f"(c[2]), "+f"(c[3])
        : "r"(a[0]), "r"(a[1]), "r"(a[2]), "r"(a[3]), "r"(b0), "r"(b1));
}
__device__ __forceinline__ uint32_t soff8(int row, int ch) {
    return (uint32_t)((row << 7) + ((ch ^ (row & 7)) << 4));
}
__device__ __forceinline__ void decode(int L, int& bi, int& bj) {
    int b = (int)((129.0f - sqrtf(16641.0f - 8.0f * (float)L)) * 0.5f);
    while (64 * (b + 1) - ((b + 1) * b) / 2 <= L) b++;
    while (64 * b - (b * (b - 1)) / 2 > L) b--;
    bi = b;
    bj = b + (L - (64 * b - (b * (b - 1)) / 2));
}
__device__ __forceinline__ void gbar(int* ctr, int tid) {
    __threadfence();
    __syncthreads();
    if (tid == 0) {
        atomicAdd(ctr, 1);
        long long n = 0;
        while (*(volatile int*)ctr < NCTA && n < (1LL << 26)) { __nanosleep(40); n++; }
    }
    __syncthreads();
    __threadfence();
}

// ---------------- fused: prep + triangle fp8 GEMM + reduction -------------------
// grid = 148, 512 threads (16 warps, 4x4 over 128x128 tile, 32x32/warp).
extern __shared__ char smem[];

__global__ void __launch_bounds__(512) k_all(const float* __restrict__ x,
                                             const int* __restrict__ t,
                                             float* __restrict__ out) {
    int tid = threadIdx.x, wid = tid >> 5, lane = tid & 31;
    int bid = blockIdx.x;
    uint32_t sb = s2u(smem);

    // ===== phase 1: zero accumulators, copy targets, normalize + e4m3 =====
    for (int idx = bid * 512 + tid; idx < 3 * Nn; idx += NCTA * 512) g_acc[idx] = 0.f;
    for (int idx = bid * 512 + tid; idx < Nn; idx += NCTA * 512) g_tgt[idx] = t[idx];
    for (int row = bid * 16 + wid; row < Nn; row += NCTA * 16) {
        float4 v = reinterpret_cast<const float4*>(x + (size_t)row * 128)[lane];
        float s = v.x * v.x + v.y * v.y + v.z * v.z + v.w * v.w;
#pragma unroll
        for (int o = 16; o; o >>= 1) s += __shfl_xor_sync(0xffffffffu, s, o);
        float inv = rsqrtf(s);
        __nv_fp8x2_storage_t lo = __nv_cvt_float2_to_fp8x2(
            make_float2(v.x * inv, v.y * inv), __NV_SATFINITE, __NV_E4M3);
        __nv_fp8x2_storage_t hi = __nv_cvt_float2_to_fp8x2(
            make_float2(v.z * inv, v.w * inv), __NV_SATFINITE, __NV_E4M3);
        reinterpret_cast<uint32_t*>(g_xq)[row * 32 + lane] =
            (uint32_t)lo | ((uint32_t)hi << 16);
    }
    gbar(&g_b1, tid);

    // ===== phase 2: persistent triangle fp8 GEMM =====
    const char* gX = (const char*)g_xq;
    int m0 = (wid & 3) * 32, n0 = (wid >> 2) * 32;

    int nstart = (int)(((long long)bid * NJOBS) / NCTA);
    int nend   = (int)(((long long)(bid + 1) * NJOBS) / NCTA);

    int bi, bj;
    decode(nstart, bi, bj);

    // prologue: A(bi)+tgtA, B(bj)+tgtB -> parity 0
#pragma unroll
    for (int q = 0; q < 2; q++) {
        int g = tid + 512 * q, row = g >> 3, ch = g & 7;
        uint32_t o = soff8(row, ch);
        cp16(sb + o,         gX + (size_t)(bi * 128 + row) * 128 + ch * 16);
        cp16(sb + 32768 + o, gX + (size_t)(bj * 128 + row) * 128 + ch * 16);
    }
    if (tid < 32)      cp16(sb + SM_TGA + tid * 16, (const char*)(g_tgt + bi * 128) + tid * 16);
    else if (tid < 64) cp16(sb + SM_TGB + (tid - 32) * 16,
                            (const char*)(g_tgt + bj * 128) + (tid - 32) * 16);
    cp_commit();

    int pa = 0, pb = 0;
    for (int L = nstart; L < nend; L++) {
        bool hn = (L + 1 < nend);
        bool aswap = false;
        if (hn) {
            int bin = bi, bjn = bj + 1;
            if (bjn == 64) { bin = bi + 1; bjn = bin; }
            if (bin != bi) {
                aswap = true;
#pragma unroll
                for (int q = 0; q < 2; q++) {
                    int g = tid + 512 * q, row = g >> 3, ch = g & 7;
                    cp16(sb + (pa ^ 1) * TS + soff8(row, ch),
                         gX + (size_t)(bin * 128 + row) * 128 + ch * 16);
                }
                if (tid < 32)
                    cp16(sb + SM_TGA + (pa ^ 1) * 512 + tid * 16,
                         (const char*)(g_tgt + bin * 128) + tid * 16);
            }
#pragma unroll
            for (int q = 0; q < 2; q++) {
                int g = tid + 512 * q, row = g >> 3, ch = g & 7;
                cp16(sb + 32768 + (pb ^ 1) * TS + soff8(row, ch),
                     gX + (size_t)(bjn * 128 + row) * 128 + ch * 16);
            }
            if (tid >= 32 && tid < 64)
                cp16(sb + SM_TGB + (pb ^ 1) * 512 + (tid - 32) * 16,
                     (const char*)(g_tgt + bjn * 128) + (tid - 32) * 16);
            cp_commit();
        }

        if (hn) cp_wait1(); else cp_wait0();
        __syncthreads();

        int i0 = bi * 128, j0 = bj * 128;
        bool diag = (bi == bj);

        float acc[2][4][4];
#pragma unroll
        for (int mf = 0; mf < 2; mf++)
#pragma unroll
            for (int nf = 0; nf < 4; nf++)
#pragma unroll
                for (int e2 = 0; e2 < 4; e2++) acc[mf][nf][e2] = 0.f;

        uint32_t Ab = sb + pa * TS, Bb = sb + 32768 + pb * TS;
        uint32_t aF[2][2][4], bF[2][2][4];
        {
            int arow = m0 + ((lane >> 3) & 1) * 8 + (lane & 7);
            int ach  = (lane >> 4);
            int brow = n0 + (lane >> 4) * 8 + (lane & 7);
            int bch  = ((lane >> 3) & 1);
            ldsm4(aF[0][0], Ab + soff8(arow,      ach));
            ldsm4(aF[0][1], Ab + soff8(arow + 16, ach));
            ldsm4(bF[0][0], Bb + soff8(brow,      bch));
            ldsm4(bF[0][1], Bb + soff8(brow + 16, bch));
#pragma unroll
            for (int ks = 0; ks < 4; ks++) {
                int c = ks & 1;
                if (ks < 3) {
                    int cn2 = c ^ 1, kn = ks + 1;
                    ldsm4(aF[cn2][0], Ab + soff8(arow,      kn * 2 + ach));
                    ldsm4(aF[cn2][1], Ab + soff8(arow + 16, kn * 2 + ach));
                    ldsm4(bF[cn2][0], Bb + soff8(brow,      kn * 2 + bch));
                    ldsm4(bF[cn2][1], Bb + soff8(brow + 16, kn * 2 + bch));
                }
#pragma unroll
                for (int mf = 0; mf < 2; mf++)
#pragma unroll
                    for (int nf2 = 0; nf2 < 2; nf2++) {
                        mma_fp8(acc[mf][nf2 * 2 + 0], aF[c][mf], bF[c][nf2][0], bF[c][nf2][1]);
                        mma_fp8(acc[mf][nf2 * 2 + 1], aF[c][mf], bF[c][nf2][2], bF[c][nf2][3]);
                    }
            }
        }

        __syncthreads();  // ldsm reads of both buffers done -> next prefetch safe

        // ---- epilogue: frag early-out + smem targets, rare path to global ----
        const int* tgA = reinterpret_cast<const int*>(smem + SM_TGA + pa * 512);
        const int* tgB = reinterpret_cast<const int*>(smem + SM_TGB + pb * 512);
#pragma unroll
        for (int nf2 = 0; nf2 < 2; nf2++)
#pragma unroll
            for (int par = 0; par < 2; par++) {
                int colb = n0 + nf2 * 16 + par * 8 + (lane & 3) * 2;
                int nf = nf2 * 2 + par;
#pragma unroll
                for (int mf = 0; mf < 2; mf++) {
                    const float* a4 = acc[mf][nf];
                    float m4 = fmaxf(fmaxf(a4[0], a4[1]), fmaxf(a4[2], a4[3]));
                    if (m4 > 0.25f) {              // rare (~1% of frags)
#pragma unroll
                        for (int h = 0; h < 2; h++) {
                            int rl = m0 + mf * 16 + h * 8 + (lane >> 2);
#pragma unroll
                            for (int e2 = 0; e2 < 2; e2++) {
                                float s = a4[h * 2 + e2];
                                if (s > 0.25f) {
                                    int gi = i0 + rl, gj = j0 + colb + e2;
                                    if (gi != gj) {  // diagonal added exactly in phase 3
                                        if (tgA[rl] == tgB[colb + e2]) {
                                            float ev = __expf(fmaf(64.f * (1.25f - s),
                                                                   s - 0.75f, -4.f));
                                            atomicAdd(&g_acc[gi], ev);
                                            if (!diag) atomicAdd(&g_acc[gj], ev);
                                        } else {
                                            float tt = s - 0.25f;
                                            float ev = __expf(fmaf(64.f * tt, tt, -36.f));
                                            atomicAdd(&g_acc[Nn + gi], ev);
                                            atomicAdd(&g_acc[2 * Nn + gi], 1.f);
                                            if (!diag) {
                                                atomicAdd(&g_acc[Nn + gj], ev);
                                                atomicAdd(&g_acc[2 * Nn + gj], 1.f);
                                            }
                                        }
                                    }
                                }
                            }
                        }
                    }
                }
            }

        pb ^= 1;
        if (aswap) pa ^= 1;
        bj++;
        if (bj == 64) { bi++; bj = bi; }
    }
    gbar(&g_b2, tid);

    // ===== phase 3: reduction on CTAs 0..31 =====
    if (bid < 32) {
        int*   hist = reinterpret_cast<int*>(smem);
        float* red  = reinterpret_cast<float*>(smem + 2048);
        hist[tid] = 0;
        __syncthreads();
        for (int i = tid; i < Nn; i += 512) atomicAdd(&hist[g_tgt[i]], 1);
        __syncthreads();

        float acc = 0.f;
        if (tid < 256) {
            int i = bid * 256 + tid;
            float spv = g_acc[i] + 1.0f;                          // exact diagonal term
            float below = (float)(Nn - hist[g_tgt[i]]) - g_acc[2 * Nn + i];
            float snv = g_acc[Nn + i] + below * NEG_C;
            float z = 40.f + logf(spv) + logf(snv);               // > 13
            acc = z + log1pf(__expf(-z));                         // softplus
        }
#pragma unroll
        for (int o = 16; o; o >>= 1) acc += __shfl_xor_sync(0xffffffffu, acc, o);
        if ((tid & 31) == 0) red[tid >> 5] = acc;
        __syncthreads();
        if (tid == 0) {
            float s = 0.f;
#pragma unroll
            for (int w = 0; w < 16; w++) s += red[w];
            g_part[bid] = s;
        }
    }
    __threadfence();
    __syncthreads();
    if (tid == 0) {
        atomicAdd(&g_b3, 1);
        if (bid == 0) {
            long long n = 0;
            while (*(volatile int*)&g_b3 < NCTA && n < (1LL << 26)) { __nanosleep(40); n++; }
            __threadfence();
            float s = 0.f;
#pragma unroll
            for (int w = 0; w < 32; w++) s += g_part[w];
            out[0] = s / (float)Nn;
            g_b1 = 0; g_b2 = 0; g_b3 = 0;   // clean state for next graph replay
            __threadfence();
        }
    }
}

extern "C" void kernel_launch(void* const* d_in, const int* in_sizes, int n_in,
                              void* d_out, int out_size) {
    const float* x  = (const float*)d_in[0];
    const int*   tg = (const int*)d_in[1];
    float* out = (float*)d_out;

    cudaFuncSetAttribute(k_all, cudaFuncAttributeMaxDynamicSharedMemorySize, SM_TOT);
    k_all<<<NCTA, 512, SM_TOT>>>(x, tg, out);
}